// round 1
// baseline (speedup 1.0000x reference)
#include <cuda_runtime.h>

// Problem constants (from reference config)
#define BB 2
#define NN 6
#define DD 48
#define FH 16
#define FW 44
#define CC 80
#define NX 256
#define NY 256
#define NCAM (BB*NN)

#define NCHUNK (CC/4)                 // 20 float4 chunks per point
#define NGROUP (BB*NN*DD*FW)          // 25344 (b,n,d,w) groups
#define NTHREAD (NGROUP*NCHUNK)       // 506880

// per-cam params: combine[9], invPost[9], trans[3], post_trans[3] = 24 floats
__device__ float g_cam[NCAM * 24];

__device__ __forceinline__ void inv3(const float* m, float* o) {
    float a = m[0], b = m[1], c = m[2];
    float d = m[3], e = m[4], f = m[5];
    float g = m[6], h = m[7], i = m[8];
    float A = e * i - f * h;
    float B = -(d * i - f * g);
    float Cc = d * h - e * g;
    float det = a * A + b * B + c * Cc;
    float id = 1.0f / det;
    o[0] = A * id;
    o[1] = -(b * i - c * h) * id;
    o[2] = (b * f - c * e) * id;
    o[3] = B * id;
    o[4] = (a * i - c * g) * id;
    o[5] = -(a * f - c * d) * id;
    o[6] = Cc * id;
    o[7] = -(a * h - b * g) * id;
    o[8] = (a * e - b * d) * id;
}

__global__ void setup_cams_kernel(const float* __restrict__ rots,
                                  const float* __restrict__ trans,
                                  const float* __restrict__ intrins,
                                  const float* __restrict__ post_rots,
                                  const float* __restrict__ post_trans) {
    int cam = blockIdx.x * blockDim.x + threadIdx.x;
    if (cam >= NCAM) return;
    float invK[9], invP[9], comb[9];
    inv3(intrins + cam * 9, invK);
    inv3(post_rots + cam * 9, invP);
    const float* R = rots + cam * 9;
    #pragma unroll
    for (int i = 0; i < 3; i++)
        #pragma unroll
        for (int k = 0; k < 3; k++)
            comb[i * 3 + k] = R[i * 3 + 0] * invK[0 * 3 + k]
                            + R[i * 3 + 1] * invK[1 * 3 + k]
                            + R[i * 3 + 2] * invK[2 * 3 + k];
    float* cp = g_cam + cam * 24;
    #pragma unroll
    for (int i = 0; i < 9; i++) cp[i] = comb[i];
    #pragma unroll
    for (int i = 0; i < 9; i++) cp[9 + i] = invP[i];
    #pragma unroll
    for (int i = 0; i < 3; i++) cp[18 + i] = trans[cam * 3 + i];
    #pragma unroll
    for (int i = 0; i < 3; i++) cp[21 + i] = post_trans[cam * 3 + i];
}

__global__ void zero_kernel(float4* __restrict__ out, int n4) {
    int i = blockIdx.x * blockDim.x + threadIdx.x;
    if (i < n4) out[i] = make_float4(0.f, 0.f, 0.f, 0.f);
}

__global__ void __launch_bounds__(256) pool_kernel(const float* __restrict__ x,
                                                   float* __restrict__ out) {
    int g = blockIdx.x * blockDim.x + threadIdx.x;
    if (g >= NTHREAD) return;

    int chunk = g % NCHUNK;
    int grp = g / NCHUNK;
    int w = grp % FW;
    int rem = grp / FW;
    int d = rem % DD;
    rem /= DD;          // rem = b*NN + n = cam
    int cam = rem;
    int b = cam / NN;

    const float* cp = g_cam + cam * 24;
    float c00 = cp[0], c01 = cp[1], c02 = cp[2];
    float c10 = cp[3], c11 = cp[4], c12 = cp[5];
    float c20 = cp[6], c21 = cp[7], c22 = cp[8];
    float p00 = cp[9], p01 = cp[10], p02 = cp[11];
    float p10 = cp[12], p11 = cp[13], p12 = cp[14];
    float p20 = cp[15], p21 = cp[16], p22 = cp[17];
    float t0 = cp[18], t1 = cp[19], t2 = cp[20];
    float pt0 = cp[21], pt1 = cp[22], pt2 = cp[23];

    // frustum coords
    float u = (float)w * (703.0f / 43.0f);       // linspace(0, 703, 44)
    float dep = 2.0f + (float)d * (56.0f / 48.0f);

    const float* xp = x + (((size_t)(cam * DD + d) * FH * FW + w) * CC) + chunk * 4;
    const int hstride = FW * CC;                 // 3520 floats

    float4 acc = make_float4(0.f, 0.f, 0.f, 0.f);
    int cur = -1;
    float* obase = out + (size_t)(b * CC + chunk * 4) * (NY * NX);

    #pragma unroll
    for (int h = 0; h < FH; h++) {
        float v = (float)h * 17.0f;              // linspace(0, 255, 16)
        // pts = frustum - post_trans
        float a0 = u - pt0, a1 = v - pt1, a2 = dep - pt2;
        // inv(post_rots) @ pts
        float q0 = p00 * a0 + p01 * a1 + p02 * a2;
        float q1 = p10 * a0 + p11 * a1 + p12 * a2;
        float q2 = p20 * a0 + p21 * a1 + p22 * a2;
        // un-normalize by depth
        float r0 = q0 * q2, r1 = q1 * q2, r2 = q2;
        // combine @ pts + trans
        float ex = c00 * r0 + c01 * r1 + c02 * r2 + t0;
        float ey = c10 * r0 + c11 * r1 + c12 * r2 + t1;
        float ez = c20 * r0 + c21 * r1 + c22 * r2 + t2;
        // voxel index: truncation toward zero matches astype(int32)
        int gx = (int)((ex + 51.2f) / 0.4f);
        int gy = (int)((ey + 51.2f) / 0.4f);
        int gz = (int)((ez + 10.0f) / 20.0f);
        bool kept = (gx >= 0) & (gx < NX) & (gy >= 0) & (gy < NY) & (gz == 0);
        if (kept) {
            int vox = gy * NX + gx;
            if (vox != cur) {
                if (cur >= 0) {
                    float* o = obase + cur;
                    atomicAdd(o, acc.x);
                    atomicAdd(o + NY * NX, acc.y);
                    atomicAdd(o + 2 * NY * NX, acc.z);
                    atomicAdd(o + 3 * NY * NX, acc.w);
                }
                acc = make_float4(0.f, 0.f, 0.f, 0.f);
                cur = vox;
            }
            float4 val = *reinterpret_cast<const float4*>(xp + h * hstride);
            acc.x += val.x;
            acc.y += val.y;
            acc.z += val.z;
            acc.w += val.w;
        }
    }
    if (cur >= 0) {
        float* o = obase + cur;
        atomicAdd(o, acc.x);
        atomicAdd(o + NY * NX, acc.y);
        atomicAdd(o + 2 * NY * NX, acc.z);
        atomicAdd(o + 3 * NY * NX, acc.w);
    }
}

extern "C" void kernel_launch(void* const* d_in, const int* in_sizes, int n_in,
                              void* d_out, int out_size) {
    const float* x          = (const float*)d_in[0];
    const float* rots       = (const float*)d_in[1];
    const float* trans      = (const float*)d_in[2];
    const float* intrins    = (const float*)d_in[3];
    const float* post_rots  = (const float*)d_in[4];
    const float* post_trans = (const float*)d_in[5];
    float* out = (float*)d_out;

    setup_cams_kernel<<<1, 32>>>(rots, trans, intrins, post_rots, post_trans);

    int n4 = out_size / 4;
    zero_kernel<<<(n4 + 255) / 256, 256>>>((float4*)out, n4);

    pool_kernel<<<(NTHREAD + 255) / 256, 256>>>(x, out);
}

// round 3
// speedup vs baseline: 1.0366x; 1.0366x over previous
#include <cuda_runtime.h>

// Problem constants (from reference config)
#define BB 2
#define NN 6
#define DD 48
#define FH 16
#define FW 44
#define CC 80
#define NX 256
#define NY 256
#define NCAM (BB*NN)

#define NCHUNK (CC/4)                 // 20 float4 chunks per point
#define NGROUP (BB*NN*DD*FW)          // 25344 (b,n,d,w) groups
#define GPB 16                        // groups per block
#define THREADS (GPB*NCHUNK)          // 320
#define NBLOCK (NGROUP/GPB)           // 1584

__device__ __forceinline__ void inv3(const float* m, float* o) {
    float a = m[0], b = m[1], c = m[2];
    float d = m[3], e = m[4], f = m[5];
    float g = m[6], h = m[7], i = m[8];
    float A = e * i - f * h;
    float B = -(d * i - f * g);
    float Cc = d * h - e * g;
    float det = a * A + b * B + c * Cc;
    float id = 1.0f / det;
    o[0] = A * id;
    o[1] = -(b * i - c * h) * id;
    o[2] = (b * f - c * e) * id;
    o[3] = B * id;
    o[4] = (a * i - c * g) * id;
    o[5] = -(a * f - c * d) * id;
    o[6] = Cc * id;
    o[7] = -(a * h - b * g) * id;
    o[8] = (a * e - b * d) * id;
}

__global__ void zero_kernel(float4* __restrict__ out, int n4) {
    int i = blockIdx.x * blockDim.x + threadIdx.x;
    if (i < n4) out[i] = make_float4(0.f, 0.f, 0.f, 0.f);
}

__global__ void __launch_bounds__(THREADS)
pool_kernel(const float* __restrict__ x,
            const float* __restrict__ rots,
            const float* __restrict__ trans,
            const float* __restrict__ intrins,
            const float* __restrict__ post_rots,
            const float* __restrict__ post_trans,
            float* __restrict__ out) {
    __shared__ int svox[GPB][FH];

    int tid = threadIdx.x;
    int gblock = blockIdx.x * GPB;

    // ---- phase 1: 16 threads compute per-group geometry (voxel index per h) ----
    if (tid < GPB) {
        int grp = gblock + tid;
        int w = grp % FW;
        int rem = grp / FW;
        int d = rem % DD;
        int cam = rem / DD;

        float invK[9], invP[9], comb[9];
        inv3(intrins + cam * 9, invK);
        inv3(post_rots + cam * 9, invP);
        const float* R = rots + cam * 9;
        #pragma unroll
        for (int i = 0; i < 3; i++)
            #pragma unroll
            for (int k = 0; k < 3; k++)
                comb[i * 3 + k] = R[i * 3 + 0] * invK[0 * 3 + k]
                                + R[i * 3 + 1] * invK[1 * 3 + k]
                                + R[i * 3 + 2] * invK[2 * 3 + k];
        float t0 = trans[cam * 3 + 0], t1 = trans[cam * 3 + 1], t2 = trans[cam * 3 + 2];
        float pt0 = post_trans[cam * 3 + 0], pt1 = post_trans[cam * 3 + 1], pt2 = post_trans[cam * 3 + 2];

        float u = (float)w * (703.0f / 43.0f);       // linspace(0, 703, 44)
        float dep = 2.0f + (float)d * (56.0f / 48.0f);

        #pragma unroll
        for (int h = 0; h < FH; h++) {
            float v = (float)h * 17.0f;              // linspace(0, 255, 16)
            float a0 = u - pt0, a1 = v - pt1, a2 = dep - pt2;
            float q0 = invP[0] * a0 + invP[1] * a1 + invP[2] * a2;
            float q1 = invP[3] * a0 + invP[4] * a1 + invP[5] * a2;
            float q2 = invP[6] * a0 + invP[7] * a1 + invP[8] * a2;
            float r0 = q0 * q2, r1 = q1 * q2, r2 = q2;
            float ex = comb[0] * r0 + comb[1] * r1 + comb[2] * r2 + t0;
            float ey = comb[3] * r0 + comb[4] * r1 + comb[5] * r2 + t1;
            float ez = comb[6] * r0 + comb[7] * r1 + comb[8] * r2 + t2;
            // truncation toward zero matches astype(int32)
            int gx = (int)((ex + 51.2f) / 0.4f);
            int gy = (int)((ey + 51.2f) / 0.4f);
            int gz = (int)((ez + 10.0f) / 20.0f);
            bool kept = (gx >= 0) & (gx < NX) & (gy >= 0) & (gy < NY) & (gz == 0);
            svox[tid][h] = kept ? (gy * NX + gx) : -1;
        }
    }
    __syncthreads();

    // ---- phase 2: 320 threads = 16 groups x 20 chunks accumulate features ----
    int g_local = tid / NCHUNK;
    int chunk = tid - g_local * NCHUNK;
    int grp = gblock + g_local;
    int w = grp % FW;
    int rem = grp / FW;
    int d = rem % DD;
    int cam = rem / DD;
    int b = cam / NN;

    const float* xp = x + (((size_t)(cam * DD + d) * FH * FW + w) * CC) + chunk * 4;
    const int hstride = FW * CC;                 // 3520 floats
    float* obase = out + (size_t)(b * CC + chunk * 4) * (NY * NX);

    float4 acc = make_float4(0.f, 0.f, 0.f, 0.f);
    int cur = -1;

    #pragma unroll
    for (int h = 0; h < FH; h++) {
        int vox = svox[g_local][h];
        if (vox >= 0) {
            if (vox != cur) {
                if (cur >= 0) {
                    float* o = obase + cur;
                    atomicAdd(o, acc.x);
                    atomicAdd(o + NY * NX, acc.y);
                    atomicAdd(o + 2 * NY * NX, acc.z);
                    atomicAdd(o + 3 * NY * NX, acc.w);
                }
                acc = make_float4(0.f, 0.f, 0.f, 0.f);
                cur = vox;
            }
            float4 val = *reinterpret_cast<const float4*>(xp + h * hstride);
            acc.x += val.x;
            acc.y += val.y;
            acc.z += val.z;
            acc.w += val.w;
        }
    }
    if (cur >= 0) {
        float* o = obase + cur;
        atomicAdd(o, acc.x);
        atomicAdd(o + NY * NX, acc.y);
        atomicAdd(o + 2 * NY * NX, acc.z);
        atomicAdd(o + 3 * NY * NX, acc.w);
    }
}

extern "C" void kernel_launch(void* const* d_in, const int* in_sizes, int n_in,
                              void* d_out, int out_size) {
    const float* x          = (const float*)d_in[0];
    const float* rots       = (const float*)d_in[1];
    const float* trans      = (const float*)d_in[2];
    const float* intrins    = (const float*)d_in[3];
    const float* post_rots  = (const float*)d_in[4];
    const float* post_trans = (const float*)d_in[5];
    float* out = (float*)d_out;

    int n4 = out_size / 4;
    zero_kernel<<<(n4 + 255) / 256, 256>>>((float4*)out, n4);

    pool_kernel<<<NBLOCK, THREADS>>>(x, rots, trans, intrins, post_rots, post_trans, out);
}

// round 4
// speedup vs baseline: 1.2657x; 1.2211x over previous
#include <cuda_runtime.h>

// Problem constants (from reference config)
#define BB 2
#define NN 6
#define DD 48
#define FH 16
#define FW 44
#define CC 80
#define NX 256
#define NY 256
#define NCAM (BB*NN)

#define NCHUNK (CC/4)                 // 20 float4 chunks per point
#define NGROUP (BB*NN*DD*FW)          // 25344 (b,n,d,w) groups
#define GPB 16                        // groups per block
#define THREADS (GPB*NCHUNK)          // 320
#define NBLOCK (NGROUP/GPB)           // 1584

__device__ __forceinline__ void inv3(const float* m, float* o) {
    float a = m[0], b = m[1], c = m[2];
    float d = m[3], e = m[4], f = m[5];
    float g = m[6], h = m[7], i = m[8];
    float A = e * i - f * h;
    float B = -(d * i - f * g);
    float Cc = d * h - e * g;
    float det = a * A + b * B + c * Cc;
    float id = 1.0f / det;
    o[0] = A * id;
    o[1] = -(b * i - c * h) * id;
    o[2] = (b * f - c * e) * id;
    o[3] = B * id;
    o[4] = (a * i - c * g) * id;
    o[5] = -(a * f - c * d) * id;
    o[6] = Cc * id;
    o[7] = -(a * h - b * g) * id;
    o[8] = (a * e - b * d) * id;
}

__global__ void __launch_bounds__(THREADS)
pool_kernel(const float* __restrict__ x,
            const float* __restrict__ rots,
            const float* __restrict__ trans,
            const float* __restrict__ intrins,
            const float* __restrict__ post_rots,
            const float* __restrict__ post_trans,
            float* __restrict__ out) {
    __shared__ int svox[GPB][FH];
    __shared__ int sclass[GPB];   // 0 = all dropped, 1 = uniform valid, 2 = mixed

    int tid = threadIdx.x;
    int gblock = blockIdx.x * GPB;

    // ---- phase 1: 16 threads compute per-group geometry (voxel index per h) ----
    if (tid < GPB) {
        int grp = gblock + tid;
        int w = grp % FW;
        int rem = grp / FW;
        int d = rem % DD;
        int cam = rem / DD;

        float invK[9], invP[9], comb[9];
        inv3(intrins + cam * 9, invK);
        inv3(post_rots + cam * 9, invP);
        const float* R = rots + cam * 9;
        #pragma unroll
        for (int i = 0; i < 3; i++)
            #pragma unroll
            for (int k = 0; k < 3; k++)
                comb[i * 3 + k] = R[i * 3 + 0] * invK[0 * 3 + k]
                                + R[i * 3 + 1] * invK[1 * 3 + k]
                                + R[i * 3 + 2] * invK[2 * 3 + k];
        float t0 = trans[cam * 3 + 0], t1 = trans[cam * 3 + 1], t2 = trans[cam * 3 + 2];
        float pt0 = post_trans[cam * 3 + 0], pt1 = post_trans[cam * 3 + 1], pt2 = post_trans[cam * 3 + 2];

        float u = (float)w * (703.0f / 43.0f);       // linspace(0, 703, 44)
        float dep = 2.0f + (float)d * (56.0f / 48.0f);

        int first = -2;
        bool uniform = true;
        bool anyvalid = false;
        #pragma unroll
        for (int h = 0; h < FH; h++) {
            float v = (float)h * 17.0f;              // linspace(0, 255, 16)
            float a0 = u - pt0, a1 = v - pt1, a2 = dep - pt2;
            float q0 = invP[0] * a0 + invP[1] * a1 + invP[2] * a2;
            float q1 = invP[3] * a0 + invP[4] * a1 + invP[5] * a2;
            float q2 = invP[6] * a0 + invP[7] * a1 + invP[8] * a2;
            float r0 = q0 * q2, r1 = q1 * q2, r2 = q2;
            float ex = comb[0] * r0 + comb[1] * r1 + comb[2] * r2 + t0;
            float ey = comb[3] * r0 + comb[4] * r1 + comb[5] * r2 + t1;
            float ez = comb[6] * r0 + comb[7] * r1 + comb[8] * r2 + t2;
            // truncation toward zero matches astype(int32)
            int gx = (int)((ex + 51.2f) / 0.4f);
            int gy = (int)((ey + 51.2f) / 0.4f);
            int gz = (int)((ez + 10.0f) / 20.0f);
            bool kept = (gx >= 0) & (gx < NX) & (gy >= 0) & (gy < NY) & (gz == 0);
            int vox = kept ? (gy * NX + gx) : -1;
            svox[tid][h] = vox;
            if (h == 0) first = vox;
            else uniform &= (vox == first);
            anyvalid |= kept;
        }
        sclass[tid] = !anyvalid ? 0 : ((uniform && first >= 0) ? 1 : 2);
    }
    __syncthreads();

    // ---- phase 2: 320 threads = 16 groups x 20 chunks accumulate features ----
    int g_local = tid / NCHUNK;
    int chunk = tid - g_local * NCHUNK;
    int cls = sclass[g_local];
    if (cls == 0) return;                        // whole column out of bounds: no loads

    int grp = gblock + g_local;
    int w = grp % FW;
    int rem = grp / FW;
    int d = rem % DD;
    int cam = rem / DD;
    int b = cam / NN;

    const float* xp = x + (((size_t)(cam * DD + d) * FH * FW + w) * CC) + chunk * 4;
    const int hstride = FW * CC;                 // 3520 floats
    float* obase = out + (size_t)(b * CC + chunk * 4) * (NY * NX);

    if (cls == 1) {
        // uniform column: branch-free, 16 independent streaming loads (MLP=16)
        float4 acc = make_float4(0.f, 0.f, 0.f, 0.f);
        #pragma unroll
        for (int h = 0; h < FH; h++) {
            float4 val = __ldcs(reinterpret_cast<const float4*>(xp + h * hstride));
            acc.x += val.x;
            acc.y += val.y;
            acc.z += val.z;
            acc.w += val.w;
        }
        int vox = svox[g_local][0];
        float* o = obase + vox;
        atomicAdd(o, acc.x);
        atomicAdd(o + NY * NX, acc.y);
        atomicAdd(o + 2 * NY * NX, acc.z);
        atomicAdd(o + 3 * NY * NX, acc.w);
        return;
    }

    // mixed column (rare): run-length accumulate
    float4 acc = make_float4(0.f, 0.f, 0.f, 0.f);
    int cur = -1;
    #pragma unroll
    for (int h = 0; h < FH; h++) {
        int vox = svox[g_local][h];
        if (vox >= 0) {
            if (vox != cur) {
                if (cur >= 0) {
                    float* o = obase + cur;
                    atomicAdd(o, acc.x);
                    atomicAdd(o + NY * NX, acc.y);
                    atomicAdd(o + 2 * NY * NX, acc.z);
                    atomicAdd(o + 3 * NY * NX, acc.w);
                }
                acc = make_float4(0.f, 0.f, 0.f, 0.f);
                cur = vox;
            }
            float4 val = __ldcs(reinterpret_cast<const float4*>(xp + h * hstride));
            acc.x += val.x;
            acc.y += val.y;
            acc.z += val.z;
            acc.w += val.w;
        }
    }
    if (cur >= 0) {
        float* o = obase + cur;
        atomicAdd(o, acc.x);
        atomicAdd(o + NY * NX, acc.y);
        atomicAdd(o + 2 * NY * NX, acc.z);
        atomicAdd(o + 3 * NY * NX, acc.w);
    }
}

extern "C" void kernel_launch(void* const* d_in, const int* in_sizes, int n_in,
                              void* d_out, int out_size) {
    const float* x          = (const float*)d_in[0];
    const float* rots       = (const float*)d_in[1];
    const float* trans      = (const float*)d_in[2];
    const float* intrins    = (const float*)d_in[3];
    const float* post_rots  = (const float*)d_in[4];
    const float* post_trans = (const float*)d_in[5];
    float* out = (float*)d_out;

    cudaMemsetAsync(out, 0, (size_t)out_size * sizeof(float));

    pool_kernel<<<NBLOCK, THREADS>>>(x, rots, trans, intrins, post_rots, post_trans, out);
}